// round 17
// baseline (speedup 1.0000x reference)
#include <cuda_runtime.h>
#include <cuda_bf16.h>
#include <cstdint>
#include <math.h>

#define NROWS 16384
#define HDIM  4096
#define NEXP  64
#define KC    64
#define NCHUNK (HDIM / KC)      // 64
#define TM    128               // rows per block
#define NTHR  256               // 8 warps
#define NBLK  (NROWS / TM)      // 128 blocks, single wave

#define APITCH  144             // bytes per smem row (64 bf16 + 16B pad)
#define A_SPLIT (TM * APITCH)   // 18432 B per A split
#define B_SPLIT (NEXP * APITCH) // 9216 B per B split
#define SM_B0   (2 * A_SPLIT)   // 36864 (B region within one buffer)
#define BUF_BYTES (2 * A_SPLIT + 2 * B_SPLIT)   // 55296 per stage
#define SM_TOTAL (2 * BUF_BYTES)                 // 110592
#define LPITCH  65              // logits smem pitch (floats)

// Pre-split W: 2 bf16 terms (round-to-nearest), [split][e*HDIM + k]. 1 MB.
__device__ __nv_bfloat16 g_ws[2][NEXP * HDIM];

__device__ __forceinline__ uint32_t smem_u32(const void* p) {
    uint32_t a;
    asm("{ .reg .u64 t; cvta.to.shared.u64 t, %1; cvt.u32.u64 %0, t; }" : "=r"(a) : "l"(p));
    return a;
}
__device__ __forceinline__ void ldsm4(uint32_t* r, uint32_t addr) {
    asm volatile("ldmatrix.sync.aligned.m8n8.x4.shared.b16 {%0,%1,%2,%3}, [%4];"
                 : "=r"(r[0]), "=r"(r[1]), "=r"(r[2]), "=r"(r[3]) : "r"(addr));
}
__device__ __forceinline__ void mma16816(float* c, const uint32_t* a, const uint32_t* b) {
    asm volatile("mma.sync.aligned.m16n8k16.row.col.f32.bf16.bf16.f32 "
                 "{%0,%1,%2,%3}, {%4,%5,%6,%7}, {%8,%9}, {%0,%1,%2,%3};"
                 : "+f"(c[0]), "+f"(c[1]), "+f"(c[2]), "+f"(c[3])
                 : "r"(a[0]), "r"(a[1]), "r"(a[2]), "r"(a[3]), "r"(b[0]), "r"(b[1]));
}
__device__ __forceinline__ uint32_t pack_rn(float f0, float f1) {
    uint32_t r;
    asm("cvt.rn.bf16x2.f32 %0, %1, %2;" : "=r"(r) : "f"(f1), "f"(f0));
    return r;
}
#define CP_ASYNC16(dst, src) \
    asm volatile("cp.async.cg.shared.global [%0], [%1], 16;" :: "r"(dst), "l"(src) : "memory")
#define CP_COMMIT() asm volatile("cp.async.commit_group;" ::: "memory")
#define CP_WAIT0()  asm volatile("cp.async.wait_group 0;" ::: "memory")

__global__ void split_w_kernel(const float* __restrict__ W) {
    int idx = blockIdx.x * 256 + threadIdx.x;
    if (idx >= NEXP * HDIM) return;
    float v = W[idx];
    __nv_bfloat16 h1 = __float2bfloat16(v);               // round-to-nearest
    float r = v - __bfloat162float(h1);                    // exact residual
    g_ws[0][idx] = h1;
    g_ws[1][idx] = __float2bfloat16(r);
}

__global__ void __launch_bounds__(NTHR, 1)
router_hmma(const float* __restrict__ x,
            float* __restrict__ scores, float* __restrict__ wout,
            float* __restrict__ iout)
{
    extern __shared__ __align__(16) char sm[];
    const uint32_t smb = smem_u32(sm);

    const int tid = threadIdx.x;
    const int l   = tid & 31;
    const int w   = tid >> 5;
    const int mt  = w & 3;          // m-tile group: rows mt*32 .. +31
    const int nh  = w >> 2;         // n-half: experts nh*32 .. +31
    const int row0 = blockIdx.x * TM;

    float acc[2][4][4];
#pragma unroll
    for (int t = 0; t < 2; t++)
#pragma unroll
        for (int n = 0; n < 4; n++)
#pragma unroll
            for (int i = 0; i < 4; i++) acc[t][n][i] = 0.f;

    // ldmatrix lane-address bases (relative to buffer start)
    const uint32_t a_rel = (uint32_t)((mt * 32 + (l & 15)) * APITCH + (l >> 4) * 16);
    const uint32_t b_rel = (uint32_t)(SM_B0 +
        (nh * 32 + (l & 7) + ((l >> 4) & 1) * 8) * APITCH + ((l >> 3) & 1) * 16);

    // ---- x loader: warp w covers rows [w*16, w*16+16); per instr j, lanes read
    //      512B contiguous (2 rows x 256B; lane = one float4 quarter) ----
    const int xr   = (l >> 4);          // row-within-pair
    const int xq   = (l & 15);          // 16B quarter within the 256B row-chunk
    const float* xbase = x + (size_t)(row0 + w * 16 + xr) * HDIM + xq * 4;
    const uint32_t aoff = (uint32_t)((w * 16 + xr) * APITCH + xq * 8);

    // ---- B loader (cp.async): lanes 0-7 cover one expert row's 128B chunk ----
    const char* bgsrc[4];
    uint32_t    bsoff[4];
#pragma unroll
    for (int p = 0; p < 4; p++) {
        int g  = w * 16 + p * 4 + (l >> 3);   // 0..127 expert-row id
        int sp = g >> 6;
        int e  = g & 63;
        bgsrc[p] = (const char*)(g_ws[sp] + (size_t)e * HDIM) + (l & 7) * 16;
        bsoff[p] = (uint32_t)(SM_B0 + sp * B_SPLIT + e * APITCH + (l & 7) * 16);
    }

    float4 xv[8];

    // ---- prologue: B chunk0 via cp.async; x chunk0 -> convert -> buf0 ----
#pragma unroll
    for (int p = 0; p < 4; p++) CP_ASYNC16(smb + bsoff[p], bgsrc[p]);
    CP_COMMIT();
#pragma unroll
    for (int j = 0; j < 8; j++)
        xv[j] = *(const float4*)(xbase + (size_t)(j * 2) * HDIM);
    {
        char* buf = sm;
#pragma unroll
        for (int j = 0; j < 8; j++) {
            float4 f = xv[j];
            uint32_t u1 = pack_rn(f.x, f.y), v1 = pack_rn(f.z, f.w);
            uint32_t u2 = pack_rn(f.x - __uint_as_float(u1 << 16),
                                  f.y - __uint_as_float(u1 & 0xFFFF0000u));
            uint32_t v2 = pack_rn(f.z - __uint_as_float(v1 << 16),
                                  f.w - __uint_as_float(v1 & 0xFFFF0000u));
            uint2 s1 = {u1, v1}, s2 = {u2, v2};
            *(uint2*)(buf + aoff + j * (2 * APITCH))           = s1;
            *(uint2*)(buf + A_SPLIT + aoff + j * (2 * APITCH)) = s2;
        }
    }
    // prefetch x chunk 1
#pragma unroll
    for (int j = 0; j < 8; j++)
        xv[j] = *(const float4*)(xbase + (size_t)(j * 2) * HDIM + KC);
    CP_WAIT0();
    __syncthreads();

    // ---- double-buffered fragment registers ----
    uint32_t A0[2][8], A1[2][8], B0[2][8], B1[2][8];

    for (int c = 0; c < NCHUNK; c++) {
        const uint32_t bufb = smb + (uint32_t)((c & 1) * BUF_BYTES);
        char* nbuf = sm + ((c + 1) & 1) * BUF_BYTES;
        const uint32_t nbufb = smb + (uint32_t)(((c + 1) & 1) * BUF_BYTES);

        // ---- issue B cp.async for chunk c+1 early (overlaps MMA phase) ----
        if (c + 1 < NCHUNK) {
#pragma unroll
            for (int p = 0; p < 4; p++)
                CP_ASYNC16(nbufb + bsoff[p], bgsrc[p] + (size_t)(c + 1) * (KC * 2));
            CP_COMMIT();
        }

        // ---- preload frags for ks=0 ----
        ldsm4(A0[0],     bufb + a_rel);
        ldsm4(A0[0] + 4, bufb + a_rel + 2304);
        ldsm4(A1[0],     bufb + A_SPLIT + a_rel);
        ldsm4(A1[0] + 4, bufb + A_SPLIT + a_rel + 2304);
        ldsm4(B0[0],     bufb + b_rel);
        ldsm4(B0[0] + 4, bufb + b_rel + 2304);
        ldsm4(B1[0],     bufb + B_SPLIT + b_rel);
        ldsm4(B1[0] + 4, bufb + B_SPLIT + b_rel + 2304);

#pragma unroll
        for (int ks = 0; ks < 4; ks++) {
            const int cur = ks & 1, nxt = cur ^ 1;

            // ---- issue ldsm for ks+1 first; latency hides under cur's MMAs ----
            if (ks < 3) {
                const uint32_t ko = (uint32_t)((ks + 1) * 32);
                ldsm4(A0[nxt],     bufb + a_rel + ko);
                ldsm4(A0[nxt] + 4, bufb + a_rel + 2304 + ko);
                ldsm4(A1[nxt],     bufb + A_SPLIT + a_rel + ko);
                ldsm4(A1[nxt] + 4, bufb + A_SPLIT + a_rel + 2304 + ko);
                ldsm4(B0[nxt],     bufb + b_rel + ko);
                ldsm4(B0[nxt] + 4, bufb + b_rel + 2304 + ko);
                ldsm4(B1[nxt],     bufb + B_SPLIT + b_rel + ko);
                ldsm4(B1[nxt] + 4, bufb + B_SPLIT + b_rel + 2304 + ko);
            }

            if (ks == 0) {
                // ---- convert + store A chunk c+1 into the other buffer ----
                if (c + 1 < NCHUNK) {
#pragma unroll
                    for (int j = 0; j < 8; j++) {
                        float4 f = xv[j];
                        uint32_t u1 = pack_rn(f.x, f.y), v1 = pack_rn(f.z, f.w);
                        uint32_t u2 = pack_rn(f.x - __uint_as_float(u1 << 16),
                                              f.y - __uint_as_float(u1 & 0xFFFF0000u));
                        uint32_t v2 = pack_rn(f.z - __uint_as_float(v1 << 16),
                                              f.w - __uint_as_float(v1 & 0xFFFF0000u));
                        uint2 s1 = {u1, v1}, s2 = {u2, v2};
                        *(uint2*)(nbuf + aoff + j * (2 * APITCH))           = s1;
                        *(uint2*)(nbuf + A_SPLIT + aoff + j * (2 * APITCH)) = s2;
                    }
                }
                // ---- prefetch x chunk c+2 ----
                if (c + 2 < NCHUNK) {
#pragma unroll
                    for (int j = 0; j < 8; j++)
                        xv[j] = *(const float4*)(xbase + (size_t)(j * 2) * HDIM
                                                 + (size_t)(c + 2) * KC);
                }
            }

            // ---- MMAs for cur (frags ready); product-outer: 8 indep accs ----
#pragma unroll
            for (int t = 0; t < 2; t++)
#pragma unroll
                for (int n = 0; n < 4; n++) mma16816(acc[t][n], A0[cur] + t * 4, B0[cur] + n * 2);
#pragma unroll
            for (int t = 0; t < 2; t++)
#pragma unroll
                for (int n = 0; n < 4; n++) mma16816(acc[t][n], A0[cur] + t * 4, B1[cur] + n * 2);
#pragma unroll
            for (int t = 0; t < 2; t++)
#pragma unroll
                for (int n = 0; n < 4; n++) mma16816(acc[t][n], A1[cur] + t * 4, B0[cur] + n * 2);
        }
        if (c + 1 < NCHUNK) { CP_WAIT0(); }
        __syncthreads();   // stores/cp.async for c+1 visible; all ldsm of c done
    }

    // ---- scatter accumulators (logits) to smem (buf0 region) ----
    float* ls = (float*)sm;
#pragma unroll
    for (int t = 0; t < 2; t++)
#pragma unroll
        for (int n = 0; n < 4; n++)
#pragma unroll
            for (int i = 0; i < 4; i++) {
                int r  = mt * 32 + t * 16 + (l >> 2) + (i >> 1) * 8;
                int cc = nh * 32 + n * 8 + (l & 3) * 2 + (i & 1);
                ls[r * LPITCH + cc] = acc[t][n][i];
            }
    __syncthreads();

    // ---- per-row softmax + top-2 + p1 norm (threads 0..127 own rows) ----
    if (tid < TM) {
        const int row = row0 + tid;
        float d[64];
#pragma unroll
        for (int e = 0; e < 64; e++) d[e] = ls[tid * LPITCH + e];

        float mx = d[0];
#pragma unroll
        for (int e = 1; e < 64; e++) mx = fmaxf(mx, d[e]);
        float sum = 0.f;
#pragma unroll
        for (int e = 0; e < 64; e++) sum += expf(d[e] - mx);
        const float inv = 1.f / sum;

        float v1 = -INFINITY, v2 = -INFINITY; int i1 = 0, i2 = 0;
#pragma unroll
        for (int e = 0; e < 64; e++) {
            float lg = d[e];
            if (lg > v1)      { v2 = v1; i2 = i1; v1 = lg; i1 = e; }
            else if (lg > v2) { v2 = lg; i2 = e; }
        }

        float* srow = scores + (size_t)row * NEXP;
#pragma unroll
        for (int q = 0; q < 16; q++) {
            float4 o;
            o.x = expf(d[4 * q + 0] - mx) * inv;
            o.y = expf(d[4 * q + 1] - mx) * inv;
            o.z = expf(d[4 * q + 2] - mx) * inv;
            o.w = expf(d[4 * q + 3] - mx) * inv;
            ((float4*)srow)[q] = o;
        }

        const float p1 = expf(v1 - mx) * inv;
        const float p2 = expf(v2 - mx) * inv;
        const float ns = 1.f / (p1 + p2);
        wout[row * 2 + 0] = p1 * ns;
        wout[row * 2 + 1] = p2 * ns;
        iout[row * 2 + 0] = (float)i1;
        iout[row * 2 + 1] = (float)i2;
    }
}

extern "C" void kernel_launch(void* const* d_in, const int* in_sizes, int n_in,
                              void* d_out, int out_size)
{
    const float* x = (const float*)d_in[0];
    const float* W = (const float*)d_in[1];

    float* out    = (float*)d_out;
    float* scores = out;                          // [N, E]
    float* wout   = out + (size_t)NROWS * NEXP;   // [N, 2]
    float* iout   = wout + (size_t)NROWS * 2;     // [N, 2] (value-cast indices)

    cudaFuncSetAttribute(router_hmma,
                         cudaFuncAttributeMaxDynamicSharedMemorySize, SM_TOTAL);

    split_w_kernel<<<(NEXP * HDIM + 255) / 256, 256>>>(W);
    router_hmma<<<NBLK, NTHR, SM_TOTAL>>>(x, scores, wout, iout);
}